// round 4
// baseline (speedup 1.0000x reference)
#include <cuda_runtime.h>
#include <math.h>

// Problem constants
constexpr int Mtok  = 2048;   // tokens
constexpr int Kdim  = 2048;   // hidden
constexpr int Ndim  = 1408;   // intermediate
constexpr int NE    = 8;      // experts
constexpr int TOPK  = 2;
constexpr int CAP   = 1024;   // 2 * (M*TOPK/E)
constexpr int RROWS = Mtok * TOPK;   // 4096

// GEMM tiling
constexpr int BM = 128;
constexpr int BN = 64;
constexpr int BK = 16;

// Scratch (device globals: no allocation allowed in kernel_launch)
__device__ int   g_count[NE];
__device__ int   g_rowtok[NE * CAP];
__device__ float g_rowgate[NE * CAP];
__device__ float g_h[(size_t)NE * CAP * Ndim];   // ~46 MB intermediate activations

// ---------------------------------------------------------------------------
// Kernel 0: zero output + expert counters
// ---------------------------------------------------------------------------
__global__ void k_zero(float* __restrict__ out) {
    int idx = blockIdx.x * blockDim.x + threadIdx.x;
    if (idx < Mtok * Kdim / 4) {
        float4 z = make_float4(0.f, 0.f, 0.f, 0.f);
        reinterpret_cast<float4*>(out)[idx] = z;
    }
    if (idx < NE) g_count[idx] = 0;
}

// ---------------------------------------------------------------------------
// Kernel 1: routing — assign each (token, slot) a position in its expert bucket
// Slot order within a bucket is nondeterministic, but each routed row's GEMM
// result is slot-independent and the combine is a fixed 2-term sum per token,
// so the output is numerically stable.
// ---------------------------------------------------------------------------
__global__ void k_route(const int* __restrict__ flat_idx,
                        const float* __restrict__ flat_gate) {
    int r = blockIdx.x * blockDim.x + threadIdx.x;
    if (r >= RROWS) return;
    int e = flat_idx[r];
    if (e < 0 || e >= NE) return;
    int pos = atomicAdd(&g_count[e], 1);
    if (pos < CAP) {
        g_rowtok[e * CAP + pos]  = r >> 1;        // token index
        g_rowgate[e * CAP + pos] = flat_gate[r];
    }
}

// ---------------------------------------------------------------------------
// Kernel 2: fused gate+up GEMM + SwiGLU
//   g = min(X_e @ GW_e^T, 10);  u = clip(X_e @ UW_e^T, -10, 10)
//   h = silu(g) * u  -> g_h (E, CAP, N)
// ---------------------------------------------------------------------------
__global__ __launch_bounds__(256)
void k_gemm1(const float* __restrict__ X,
             const float* __restrict__ GW,
             const float* __restrict__ UW) {
    const int e    = blockIdx.z;
    const int cnt  = min(g_count[e], CAP);
    const int row0 = blockIdx.y * BM;
    if (row0 >= cnt) return;
    const int n0  = blockIdx.x * BN;
    const int tid = threadIdx.x;

    __shared__ __align__(16) float As[BK][BM];
    __shared__ __align__(16) float Bg[BK][BN + 4];
    __shared__ __align__(16) float Bu[BK][BN + 4];

    // A loader: each thread loads 2 float4 from one gathered row
    const int arow = tid >> 1;              // 0..127
    const int akq  = (tid & 1) * 2;         // float4 pair {0,1} or {2,3}
    const int tok  = g_rowtok[e * CAP + row0 + arow];  // stale slots read row 0 (valid mem)
    const float4* ap4 = reinterpret_cast<const float4*>(X + (size_t)tok * Kdim);

    // B loaders: one float4 per matrix per thread
    const int brow = tid >> 2;              // 0..63
    const int bkq  = tid & 3;               // 0..3
    const float4* gp4 = reinterpret_cast<const float4*>(
        GW + ((size_t)e * Ndim + n0 + brow) * Kdim);
    const float4* up4 = reinterpret_cast<const float4*>(
        UW + ((size_t)e * Ndim + n0 + brow) * Kdim);

    const int tx = tid & 15, ty = tid >> 4;

    float accG[8][4], accU[8][4];
#pragma unroll
    for (int i = 0; i < 8; i++)
#pragma unroll
        for (int j = 0; j < 4; j++) { accG[i][j] = 0.f; accU[i][j] = 0.f; }

    const int KT = Kdim / BK;   // 128
    float4 ra0 = ap4[akq];
    float4 ra1 = ap4[akq + 1];
    float4 rg  = gp4[bkq];
    float4 ru  = up4[bkq];

    for (int kt = 0; kt < KT; ++kt) {
        __syncthreads();
        {
            int q0 = akq * 4;
            As[q0 + 0][arow] = ra0.x; As[q0 + 1][arow] = ra0.y;
            As[q0 + 2][arow] = ra0.z; As[q0 + 3][arow] = ra0.w;
            As[q0 + 4][arow] = ra1.x; As[q0 + 5][arow] = ra1.y;
            As[q0 + 6][arow] = ra1.z; As[q0 + 7][arow] = ra1.w;
            int qb = bkq * 4;
            Bg[qb + 0][brow] = rg.x; Bg[qb + 1][brow] = rg.y;
            Bg[qb + 2][brow] = rg.z; Bg[qb + 3][brow] = rg.w;
            Bu[qb + 0][brow] = ru.x; Bu[qb + 1][brow] = ru.y;
            Bu[qb + 2][brow] = ru.z; Bu[qb + 3][brow] = ru.w;
        }
        __syncthreads();
        if (kt + 1 < KT) {
            ra0 = ap4[(kt + 1) * 4 + akq];
            ra1 = ap4[(kt + 1) * 4 + akq + 1];
            rg  = gp4[(kt + 1) * 4 + bkq];
            ru  = up4[(kt + 1) * 4 + bkq];
        }
#pragma unroll
        for (int kk = 0; kk < BK; ++kk) {
            float4 a0 = *reinterpret_cast<const float4*>(&As[kk][ty * 8]);
            float4 a1 = *reinterpret_cast<const float4*>(&As[kk][ty * 8 + 4]);
            float4 b0 = *reinterpret_cast<const float4*>(&Bg[kk][tx * 4]);
            float4 b1 = *reinterpret_cast<const float4*>(&Bu[kk][tx * 4]);
            float a[8]  = {a0.x, a0.y, a0.z, a0.w, a1.x, a1.y, a1.z, a1.w};
            float bgv[4] = {b0.x, b0.y, b0.z, b0.w};
            float buv[4] = {b1.x, b1.y, b1.z, b1.w};
#pragma unroll
            for (int i = 0; i < 8; i++)
#pragma unroll
                for (int j = 0; j < 4; j++) {
                    accG[i][j] = fmaf(a[i], bgv[j], accG[i][j]);
                    accU[i][j] = fmaf(a[i], buv[j], accU[i][j]);
                }
        }
    }

    // SwiGLU epilogue -> g_h
#pragma unroll
    for (int i = 0; i < 8; i++) {
        int gr = row0 + ty * 8 + i;
        float4 hv;
        float* h = &hv.x;
#pragma unroll
        for (int j = 0; j < 4; j++) {
            float g = fminf(accG[i][j], 10.f);
            float u = fminf(fmaxf(accU[i][j], -10.f), 10.f);
            float s = g / (1.f + expf(-g));   // silu
            h[j] = s * u;
        }
        *reinterpret_cast<float4*>(
            g_h + ((size_t)e * CAP + gr) * Ndim + n0 + tx * 4) = hv;
    }
}

// ---------------------------------------------------------------------------
// Kernel 3: down GEMM + fused gated scatter-combine
//   d = h @ DW_e^T (over N);  out[tok] += gate * d-row  (2 REDG adds/elem)
// ---------------------------------------------------------------------------
__global__ __launch_bounds__(256)
void k_gemm2(const float* __restrict__ DW, float* __restrict__ out) {
    const int e    = blockIdx.z;
    const int cnt  = min(g_count[e], CAP);
    const int row0 = blockIdx.y * BM;
    if (row0 >= cnt) return;
    const int k0  = blockIdx.x * BN;
    const int tid = threadIdx.x;

    __shared__ __align__(16) float As[BK][BM];
    __shared__ __align__(16) float Bs[BK][BN + 4];

    const int arow = tid >> 1;
    const int akq  = (tid & 1) * 2;
    const float4* ap4 = reinterpret_cast<const float4*>(
        g_h + ((size_t)e * CAP + row0 + arow) * Ndim);

    const int brow = tid >> 2;
    const int bkq  = tid & 3;
    const float4* bp4 = reinterpret_cast<const float4*>(
        DW + ((size_t)e * Kdim + k0 + brow) * Ndim);

    const int tx = tid & 15, ty = tid >> 4;

    float acc[8][4];
#pragma unroll
    for (int i = 0; i < 8; i++)
#pragma unroll
        for (int j = 0; j < 4; j++) acc[i][j] = 0.f;

    const int NT = Ndim / BK;   // 88
    float4 ra0 = ap4[akq];
    float4 ra1 = ap4[akq + 1];
    float4 rb  = bp4[bkq];

    for (int nt = 0; nt < NT; ++nt) {
        __syncthreads();
        {
            int q0 = akq * 4;
            As[q0 + 0][arow] = ra0.x; As[q0 + 1][arow] = ra0.y;
            As[q0 + 2][arow] = ra0.z; As[q0 + 3][arow] = ra0.w;
            As[q0 + 4][arow] = ra1.x; As[q0 + 5][arow] = ra1.y;
            As[q0 + 6][arow] = ra1.z; As[q0 + 7][arow] = ra1.w;
            int qb = bkq * 4;
            Bs[qb + 0][brow] = rb.x; Bs[qb + 1][brow] = rb.y;
            Bs[qb + 2][brow] = rb.z; Bs[qb + 3][brow] = rb.w;
        }
        __syncthreads();
        if (nt + 1 < NT) {
            ra0 = ap4[(nt + 1) * 4 + akq];
            ra1 = ap4[(nt + 1) * 4 + akq + 1];
            rb  = bp4[(nt + 1) * 4 + bkq];
        }
#pragma unroll
        for (int kk = 0; kk < BK; ++kk) {
            float4 a0 = *reinterpret_cast<const float4*>(&As[kk][ty * 8]);
            float4 a1 = *reinterpret_cast<const float4*>(&As[kk][ty * 8 + 4]);
            float4 b0 = *reinterpret_cast<const float4*>(&Bs[kk][tx * 4]);
            float a[8] = {a0.x, a0.y, a0.z, a0.w, a1.x, a1.y, a1.z, a1.w};
            float b[4] = {b0.x, b0.y, b0.z, b0.w};
#pragma unroll
            for (int i = 0; i < 8; i++)
#pragma unroll
                for (int j = 0; j < 4; j++)
                    acc[i][j] = fmaf(a[i], b[j], acc[i][j]);
        }
    }

    // Gated scatter-combine: only valid rows contribute
#pragma unroll
    for (int i = 0; i < 8; i++) {
        int gr = row0 + ty * 8 + i;
        if (gr >= cnt) continue;
        int   tok  = g_rowtok[e * CAP + gr];
        float gate = g_rowgate[e * CAP + gr];
        float* op = out + (size_t)tok * Kdim + k0 + tx * 4;
#pragma unroll
        for (int j = 0; j < 4; j++)
            atomicAdd(op + j, gate * acc[i][j]);
    }
}

// ---------------------------------------------------------------------------
// Launch: zero -> route -> gate/up+SwiGLU -> down+combine
// ---------------------------------------------------------------------------
extern "C" void kernel_launch(void* const* d_in, const int* in_sizes, int n_in,
                              void* d_out, int out_size) {
    const float* X    = (const float*)d_in[0];  // flat_h   (M, K)
    const int*   fidx = (const int*)  d_in[1];  // flat_idx (M, TOPK)
    const float* fg   = (const float*)d_in[2];  // flat_gate(M, TOPK)
    const float* GW   = (const float*)d_in[3];  // gate_weight (E, N, K)
    const float* UW   = (const float*)d_in[4];  // up_weight   (E, N, K)
    const float* DW   = (const float*)d_in[5];  // down_weight (E, K, N)
    float* out = (float*)d_out;                 // (M, K)

    k_zero<<<(Mtok * Kdim / 4 + 255) / 256, 256>>>(out);
    k_route<<<(RROWS + 255) / 256, 256>>>(fidx, fg);

    dim3 g1(Ndim / BN, CAP / BM, NE);   // 22 x 8 x 8
    k_gemm1<<<g1, 256>>>(X, GW, UW);

    dim3 g2(Kdim / BN, CAP / BM, NE);   // 32 x 8 x 8
    k_gemm2<<<g2, 256>>>(DW, out);
}

// round 6
// speedup vs baseline: 1.3324x; 1.3324x over previous
#include <cuda_runtime.h>
#include <cstdint>
#include <math.h>

// ---------------------------------------------------------------------------
// Problem constants
// ---------------------------------------------------------------------------
constexpr int Mtok  = 2048;
constexpr int Kdim  = 2048;
constexpr int Ndim  = 1408;
constexpr int NE    = 8;
constexpr int CAP   = 1024;
constexpr int RROWS = 4096;

constexpr int SPAD  = 36;    // smem row stride in floats (padded, 16B-aligned)

// Scratch (device globals: no allocation allowed)
__device__ int   g_count[NE];
__device__ int   g_rowtok[NE * CAP];
__device__ float g_rowgate[NE * CAP];
__device__ float g_h[(size_t)NE * CAP * Ndim];   // tf32-rounded activations

// ---------------------------------------------------------------------------
// Helpers
// ---------------------------------------------------------------------------
__device__ __forceinline__ uint32_t f2tf(float x) {
    uint32_t r; asm("cvt.rna.tf32.f32 %0, %1;" : "=r"(r) : "f"(x)); return r;
}
__device__ __forceinline__ void mma8(float c[4], const uint32_t a[4],
                                     uint32_t b0, uint32_t b1) {
    asm volatile(
        "mma.sync.aligned.m16n8k8.row.col.f32.tf32.tf32.f32 "
        "{%0,%1,%2,%3}, {%4,%5,%6,%7}, {%8,%9}, {%0,%1,%2,%3};"
        : "+f"(c[0]), "+f"(c[1]), "+f"(c[2]), "+f"(c[3])
        : "r"(a[0]), "r"(a[1]), "r"(a[2]), "r"(a[3]), "r"(b0), "r"(b1));
}
__device__ __forceinline__ uint4 tf4(float4 v) {
    return make_uint4(f2tf(v.x), f2tf(v.y), f2tf(v.z), f2tf(v.w));
}

// ---------------------------------------------------------------------------
// Kernel 0/1: zero + route
// ---------------------------------------------------------------------------
__global__ void k_zero(float* __restrict__ out) {
    int idx = blockIdx.x * blockDim.x + threadIdx.x;
    if (idx < Mtok * Kdim / 4)
        reinterpret_cast<float4*>(out)[idx] = make_float4(0.f, 0.f, 0.f, 0.f);
    if (idx < NE) g_count[idx] = 0;
}
__global__ void k_route(const int* __restrict__ flat_idx,
                        const float* __restrict__ flat_gate) {
    int r = blockIdx.x * blockDim.x + threadIdx.x;
    if (r >= RROWS) return;
    int e = flat_idx[r];
    if (e < 0 || e >= NE) return;
    int pos = atomicAdd(&g_count[e], 1);
    if (pos < CAP) {
        g_rowtok[e * CAP + pos]  = r >> 1;
        g_rowgate[e * CAP + pos] = flat_gate[r];
    }
}

// ---------------------------------------------------------------------------
// Kernel 2: gate+up TF32 mma GEMM + SwiGLU -> g_h
// Block: 128 rows x 64 n (per matrix), BK=32. Warp grid 2x4, warp tile 64x16.
// ---------------------------------------------------------------------------
__global__ __launch_bounds__(256)
void k_gemm1(const float* __restrict__ X,
             const float* __restrict__ GW,
             const float* __restrict__ UW) {
    __shared__ float As[128 * SPAD];
    __shared__ float Bg[64 * SPAD];
    __shared__ float Bu[64 * SPAD];

    const int e    = blockIdx.z;
    const int cnt  = min(g_count[e], CAP);
    const int row0 = blockIdx.y * 128;
    if (row0 >= cnt) return;
    const int n0  = blockIdx.x * 64;
    const int tid = threadIdx.x;

    // ---- staging roles ----
    const int arow = tid >> 1, aseg = tid & 1;          // A: 2 thr/row, 4 x f4
    const int tok  = g_rowtok[e * CAP + row0 + arow];
    const float4* ag = reinterpret_cast<const float4*>(X + (size_t)tok * Kdim);
    const int brow = tid >> 2, bseg = tid & 3;          // B: 4 thr/row, 2 x f4
    const float4* gg = reinterpret_cast<const float4*>(
        GW + ((size_t)e * Ndim + n0 + brow) * Kdim);
    const float4* ug = reinterpret_cast<const float4*>(
        UW + ((size_t)e * Ndim + n0 + brow) * Kdim);

    // ---- compute roles ----
    const int wid = tid >> 5, lane = tid & 31;
    const int wm = (wid >> 2) * 64, wn = (wid & 3) * 16;
    const int lr = lane >> 2, lc = lane & 3;

    float accG[4][2][4], accU[4][2][4];
#pragma unroll
    for (int mf = 0; mf < 4; mf++)
#pragma unroll
        for (int nf = 0; nf < 2; nf++)
#pragma unroll
            for (int q = 0; q < 4; q++) { accG[mf][nf][q] = 0.f; accU[mf][nf][q] = 0.f; }

    const int KT = Kdim / 32;   // 64 stages
    float4 pA[4], pG[2], pU[2];
#pragma unroll
    for (int c = 0; c < 4; c++) pA[c] = ag[aseg * 4 + c];
#pragma unroll
    for (int c = 0; c < 2; c++) { pG[c] = gg[bseg * 2 + c]; pU[c] = ug[bseg * 2 + c]; }

    for (int kt = 0; kt < KT; ++kt) {
        __syncthreads();
#pragma unroll
        for (int c = 0; c < 4; c++)
            *reinterpret_cast<uint4*>(&As[arow * SPAD + aseg * 16 + c * 4]) = tf4(pA[c]);
#pragma unroll
        for (int c = 0; c < 2; c++) {
            *reinterpret_cast<uint4*>(&Bg[brow * SPAD + bseg * 8 + c * 4]) = tf4(pG[c]);
            *reinterpret_cast<uint4*>(&Bu[brow * SPAD + bseg * 8 + c * 4]) = tf4(pU[c]);
        }
        __syncthreads();
        if (kt + 1 < KT) {
            const int o = (kt + 1) * 8;
#pragma unroll
            for (int c = 0; c < 4; c++) pA[c] = ag[o + aseg * 4 + c];
#pragma unroll
            for (int c = 0; c < 2; c++) { pG[c] = gg[o + bseg * 2 + c]; pU[c] = ug[o + bseg * 2 + c]; }
        }
#pragma unroll
        for (int kk = 0; kk < 32; kk += 8) {
            uint32_t a[4][4];
#pragma unroll
            for (int mf = 0; mf < 4; mf++) {
                const int r = wm + mf * 16 + lr;
                a[mf][0] = __float_as_uint(As[r * SPAD + kk + lc]);
                a[mf][1] = __float_as_uint(As[(r + 8) * SPAD + kk + lc]);
                a[mf][2] = __float_as_uint(As[r * SPAD + kk + lc + 4]);
                a[mf][3] = __float_as_uint(As[(r + 8) * SPAD + kk + lc + 4]);
            }
#pragma unroll
            for (int nf = 0; nf < 2; nf++) {
                const int nr = wn + nf * 8 + lr;
                uint32_t g0 = __float_as_uint(Bg[nr * SPAD + kk + lc]);
                uint32_t g1 = __float_as_uint(Bg[nr * SPAD + kk + lc + 4]);
                uint32_t u0 = __float_as_uint(Bu[nr * SPAD + kk + lc]);
                uint32_t u1 = __float_as_uint(Bu[nr * SPAD + kk + lc + 4]);
#pragma unroll
                for (int mf = 0; mf < 4; mf++) {
                    mma8(accG[mf][nf], a[mf], g0, g1);
                    mma8(accU[mf][nf], a[mf], u0, u1);
                }
            }
        }
    }

    // ---- SwiGLU epilogue -> g_h (tf32-rounded) ----
#pragma unroll
    for (int mf = 0; mf < 4; mf++) {
#pragma unroll
        for (int half = 0; half < 2; half++) {       // c0/c1 vs c2/c3
            const int grow = row0 + wm + mf * 16 + lr + half * 8;
            if (grow >= cnt) continue;
            float* hrow = g_h + ((size_t)e * CAP + grow) * Ndim;
#pragma unroll
            for (int nf = 0; nf < 2; nf++) {
                const int col = n0 + wn + nf * 8 + 2 * lc;
                float2 o;
#pragma unroll
                for (int q = 0; q < 2; q++) {
                    float g = fminf(accG[mf][nf][half * 2 + q], 10.f);
                    float u = fminf(fmaxf(accU[mf][nf][half * 2 + q], -10.f), 10.f);
                    float h = (g / (1.f + expf(-g))) * u;
                    (&o.x)[q] = __uint_as_float(f2tf(h));
                }
                *reinterpret_cast<float2*>(hrow + col) = o;
            }
        }
    }
}

// ---------------------------------------------------------------------------
// Kernel 3: down TF32 mma GEMM + gated atomic combine
// Block: 128 rows x 128 k-out, BK=32 (over N). Warp grid 2x4, warp tile 64x32.
// ---------------------------------------------------------------------------
__global__ __launch_bounds__(256)
void k_gemm2(const float* __restrict__ DW, float* __restrict__ out) {
    __shared__ float As[128 * SPAD];
    __shared__ float Bs[128 * SPAD];

    const int e    = blockIdx.z;
    const int cnt  = min(g_count[e], CAP);
    const int row0 = blockIdx.y * 128;
    if (row0 >= cnt) return;
    const int k0  = blockIdx.x * 128;
    const int tid = threadIdx.x;

    const int arow = tid >> 1, aseg = tid & 1;
    const float4* ag = reinterpret_cast<const float4*>(
        g_h + ((size_t)e * CAP + row0 + arow) * Ndim);
    const float4* bg = reinterpret_cast<const float4*>(
        DW + ((size_t)e * Kdim + k0 + arow) * Ndim);

    const int wid = tid >> 5, lane = tid & 31;
    const int wm = (wid >> 2) * 64, wn = (wid & 3) * 32;
    const int lr = lane >> 2, lc = lane & 3;

    float acc[4][4][4];
#pragma unroll
    for (int mf = 0; mf < 4; mf++)
#pragma unroll
        for (int nf = 0; nf < 4; nf++)
#pragma unroll
            for (int q = 0; q < 4; q++) acc[mf][nf][q] = 0.f;

    const int KT = Ndim / 32;   // 44 stages
    float4 pA[4], pB[4];
#pragma unroll
    for (int c = 0; c < 4; c++) { pA[c] = ag[aseg * 4 + c]; pB[c] = bg[aseg * 4 + c]; }

    for (int kt = 0; kt < KT; ++kt) {
        __syncthreads();
#pragma unroll
        for (int c = 0; c < 4; c++) {
            // A already tf32-rounded in g_h: raw copy
            *reinterpret_cast<float4*>(&As[arow * SPAD + aseg * 16 + c * 4]) = pA[c];
            *reinterpret_cast<uint4*>(&Bs[arow * SPAD + aseg * 16 + c * 4]) = tf4(pB[c]);
        }
        __syncthreads();
        if (kt + 1 < KT) {
            const int o = (kt + 1) * 8;
#pragma unroll
            for (int c = 0; c < 4; c++) { pA[c] = ag[o + aseg * 4 + c]; pB[c] = bg[o + aseg * 4 + c]; }
        }
#pragma unroll
        for (int kk = 0; kk < 32; kk += 8) {
            uint32_t a[4][4];
#pragma unroll
            for (int mf = 0; mf < 4; mf++) {
                const int r = wm + mf * 16 + lr;
                a[mf][0] = __float_as_uint(As[r * SPAD + kk + lc]);
                a[mf][1] = __float_as_uint(As[(r + 8) * SPAD + kk + lc]);
                a[mf][2] = __float_as_uint(As[r * SPAD + kk + lc + 4]);
                a[mf][3] = __float_as_uint(As[(r + 8) * SPAD + kk + lc + 4]);
            }
#pragma unroll
            for (int nf = 0; nf < 4; nf++) {
                const int nr = wn + nf * 8 + lr;
                uint32_t b0 = __float_as_uint(Bs[nr * SPAD + kk + lc]);
                uint32_t b1 = __float_as_uint(Bs[nr * SPAD + kk + lc + 4]);
#pragma unroll
                for (int mf = 0; mf < 4; mf++)
                    mma8(acc[mf][nf], a[mf], b0, b1);
            }
        }
    }

    // ---- gated atomic scatter-combine ----
#pragma unroll
    for (int mf = 0; mf < 4; mf++) {
#pragma unroll
        for (int half = 0; half < 2; half++) {
            const int grow = row0 + wm + mf * 16 + lr + half * 8;
            if (grow >= cnt) continue;
            const int   tok  = g_rowtok[e * CAP + grow];
            const float gate = g_rowgate[e * CAP + grow];
            float* orow = out + (size_t)tok * Kdim + k0;
#pragma unroll
            for (int nf = 0; nf < 4; nf++) {
                const int col = wn + nf * 8 + 2 * lc;
                atomicAdd(orow + col,     gate * acc[mf][nf][half * 2]);
                atomicAdd(orow + col + 1, gate * acc[mf][nf][half * 2 + 1]);
            }
        }
    }
}

// ---------------------------------------------------------------------------
// Launch
// ---------------------------------------------------------------------------
extern "C" void kernel_launch(void* const* d_in, const int* in_sizes, int n_in,
                              void* d_out, int out_size) {
    const float* X    = (const float*)d_in[0];
    const int*   fidx = (const int*)  d_in[1];
    const float* fg   = (const float*)d_in[2];
    const float* GW   = (const float*)d_in[3];
    const float* UW   = (const float*)d_in[4];
    const float* DW   = (const float*)d_in[5];
    float* out = (float*)d_out;

    k_zero<<<(Mtok * Kdim / 4 + 255) / 256, 256>>>(out);
    k_route<<<(RROWS + 255) / 256, 256>>>(fidx, fg);

    dim3 g1(Ndim / 64, CAP / 128, NE);    // 22 x 8 x 8
    k_gemm1<<<g1, 256>>>(X, GW, UW);

    dim3 g2(Kdim / 128, CAP / 128, NE);   // 16 x 8 x 8
    k_gemm2<<<g2, 256>>>(DW, out);
}

// round 7
// speedup vs baseline: 2.2464x; 1.6860x over previous
#include <cuda_runtime.h>
#include <cstdint>
#include <math.h>

// ---------------------------------------------------------------------------
// Problem constants
// ---------------------------------------------------------------------------
constexpr int Mtok  = 2048;
constexpr int Kdim  = 2048;
constexpr int Ndim  = 1408;
constexpr int NE    = 8;
constexpr int CAP   = 1024;
constexpr int RROWS = 4096;

// Scratch
__device__ int   g_count[NE];
__device__ int   g_rowtok[NE * CAP];
__device__ float g_rowgate[NE * CAP];
__device__ float g_xr[(size_t)Mtok * Kdim];      // tf32-rounded X
__device__ float g_h[(size_t)NE * CAP * Ndim];   // tf32-rounded activations

// ---------------------------------------------------------------------------
// Helpers
// ---------------------------------------------------------------------------
__device__ __forceinline__ uint32_t smem_u32(const void* p) {
    uint32_t a;
    asm("{ .reg .u64 t; cvta.to.shared.u64 t, %1; cvt.u32.u64 %0, t; }"
        : "=r"(a) : "l"(p));
    return a;
}
__device__ __forceinline__ uint32_t f2tf(float x) {
    uint32_t r; asm("cvt.rna.tf32.f32 %0, %1;" : "=r"(r) : "f"(x)); return r;
}
__device__ __forceinline__ uint4 tf4(float4 v) {
    return make_uint4(f2tf(v.x), f2tf(v.y), f2tf(v.z), f2tf(v.w));
}
__device__ __forceinline__ void mma8(float c[4], const uint32_t a[4],
                                     uint32_t b0, uint32_t b1) {
    asm volatile(
        "mma.sync.aligned.m16n8k8.row.col.f32.tf32.tf32.f32 "
        "{%0,%1,%2,%3}, {%4,%5,%6,%7}, {%8,%9}, {%0,%1,%2,%3};"
        : "+f"(c[0]), "+f"(c[1]), "+f"(c[2]), "+f"(c[3])
        : "r"(a[0]), "r"(a[1]), "r"(a[2]), "r"(a[3]), "r"(b0), "r"(b1));
}
__device__ __forceinline__ void ldsm4(uint32_t* r, uint32_t addr) {
    asm volatile("ldmatrix.sync.aligned.m8n8.x4.shared.b16 {%0,%1,%2,%3}, [%4];"
                 : "=r"(r[0]), "=r"(r[1]), "=r"(r[2]), "=r"(r[3]) : "r"(addr));
}
__device__ __forceinline__ void cp16(uint32_t dst, const void* src) {
    asm volatile("cp.async.cg.shared.global [%0], [%1], 16;"
                 :: "r"(dst), "l"(src));
}
__device__ __forceinline__ void cp_commit() {
    asm volatile("cp.async.commit_group;" ::: "memory");
}
__device__ __forceinline__ void cp_wait0() {
    asm volatile("cp.async.wait_group 0;" ::: "memory");
}

// ---------------------------------------------------------------------------
// Small kernels: zero out, round X, route
// ---------------------------------------------------------------------------
__global__ void k_zero(float* __restrict__ out) {
    int idx = blockIdx.x * blockDim.x + threadIdx.x;
    if (idx < Mtok * Kdim / 4)
        reinterpret_cast<float4*>(out)[idx] = make_float4(0.f, 0.f, 0.f, 0.f);
    if (idx < NE) g_count[idx] = 0;
}
__global__ void k_xround(const float* __restrict__ X) {
    int idx = blockIdx.x * blockDim.x + threadIdx.x;
    if (idx < Mtok * Kdim / 4)
        reinterpret_cast<uint4*>(g_xr)[idx] =
            tf4(reinterpret_cast<const float4*>(X)[idx]);
}
__global__ void k_route(const int* __restrict__ flat_idx,
                        const float* __restrict__ flat_gate) {
    int r = blockIdx.x * blockDim.x + threadIdx.x;
    if (r >= RROWS) return;
    int e = flat_idx[r];
    if (e < 0 || e >= NE) return;
    int pos = atomicAdd(&g_count[e], 1);
    if (pos < CAP) {
        g_rowtok[e * CAP + pos]  = r >> 1;
        g_rowgate[e * CAP + pos] = flat_gate[r];
    }
}

// ---------------------------------------------------------------------------
// Kernel gemm1: gate+up, block 128 rows x 128 n (both matrices), BK=32.
// 8 warps as 2x4; warp tile = 64 rows x 32 cols for BOTH G and U.
// Double-buffered smem; A via cp.async from g_xr; weights LDG+cvt+STS.
// ---------------------------------------------------------------------------
constexpr int G1_A = 0, G1_BG = 16384, G1_BU = 32768, G1_STAGE = 49152;
constexpr int G1_SMEM = 2 * G1_STAGE;   // 96 KB

__global__ __launch_bounds__(256)
void k_gemm1(const float* __restrict__ GW, const float* __restrict__ UW) {
    extern __shared__ char smem[];
    const int e    = blockIdx.z;
    const int cnt  = min(g_count[e], CAP);
    const int row0 = blockIdx.y * 128;
    if (row0 >= cnt) return;
    const int n0  = blockIdx.x * 128;
    const int tid = threadIdx.x;
    const uint32_t sb = smem_u32(smem);

    // ---- staging ids: 8 threads per row, 1 chunk (16B) each, 4 row-passes ----
    const int srow = tid >> 3, schk = tid & 7;
    const int swz  = ((schk ^ (srow & 7)) << 4);
    int oA[4], oG[4], oU[4];
    const float* asrc[4];
#pragma unroll
    for (int p = 0; p < 4; p++) {
        const int r = srow + 32 * p;
        oA[p] = G1_A  + r * 128 + swz;
        oG[p] = G1_BG + r * 128 + swz;
        oU[p] = G1_BU + r * 128 + swz;
        int tok = g_rowtok[e * CAP + row0 + r];
        asrc[p] = g_xr + (size_t)tok * Kdim + schk * 4;
    }
    const float4* gg4 = reinterpret_cast<const float4*>(
        GW + ((size_t)e * Ndim + n0 + srow) * Kdim) + schk;
    const float4* uu4 = reinterpret_cast<const float4*>(
        UW + ((size_t)e * Ndim + n0 + srow) * Kdim) + schk;

    // ---- compute ids ----
    const int wid = tid >> 5, L = tid & 31;
    const int wm = (wid >> 2) * 64, wn = (wid & 3) * 32;
    const int lr = L >> 2, lc = L & 3;
    const int rowoffA = ((L >> 3) & 1) * 8 + (L & 7);
    const int hiA = L >> 4;
    const int rowoffB = ((L >> 4) & 1) * 8 + (L & 7);
    const int hiB = (L >> 3) & 1;
    const int lx = L & 7;
    uint32_t rA[4], rBg[2], rBu[2];
#pragma unroll
    for (int mf = 0; mf < 4; mf++)
        rA[mf] = sb + G1_A + (wm + mf * 16 + rowoffA) * 128;
#pragma unroll
    for (int h = 0; h < 2; h++) {
        rBg[h] = sb + G1_BG + (wn + h * 16 + rowoffB) * 128;
        rBu[h] = sb + G1_BU + (wn + h * 16 + rowoffB) * 128;
    }

    float accG[4][4][4], accU[4][4][4];
#pragma unroll
    for (int mf = 0; mf < 4; mf++)
#pragma unroll
        for (int nf = 0; nf < 4; nf++)
#pragma unroll
            for (int q = 0; q < 4; q++) { accG[mf][nf][q] = 0.f; accU[mf][nf][q] = 0.f; }

    // ---- prologue: stage 0 ----
#pragma unroll
    for (int p = 0; p < 4; p++) cp16(sb + oA[p], asrc[p]);
    cp_commit();
    float4 pg[4], pu[4];
#pragma unroll
    for (int p = 0; p < 4; p++) {
        pg[p] = gg4[(size_t)p * 16384];
        pu[p] = uu4[(size_t)p * 16384];
    }
#pragma unroll
    for (int p = 0; p < 4; p++) {
        *reinterpret_cast<uint4*>(smem + oG[p]) = tf4(pg[p]);
        *reinterpret_cast<uint4*>(smem + oU[p]) = tf4(pu[p]);
    }
    cp_wait0();
    __syncthreads();

    const int KT = Kdim / 32;   // 64
    for (int kt = 0; kt < KT; ++kt) {
        const int cur = (kt & 1) * G1_STAGE;
        const int nxt = ((kt + 1) & 1) * G1_STAGE;
        const bool more = (kt + 1 < KT);
        if (more) {
#pragma unroll
            for (int p = 0; p < 4; p++)
                cp16(sb + nxt + oA[p], asrc[p] + (kt + 1) * 32);
            cp_commit();
        }
#pragma unroll
        for (int c = 0; c < 4; c++) {
            uint32_t a[4][4], bg[2][4], bu[2][4];
            const uint32_t swA = (uint32_t)(((2 * c + hiA) ^ lx) << 4) + cur;
            const uint32_t swB = (uint32_t)(((2 * c + hiB) ^ lx) << 4) + cur;
#pragma unroll
            for (int mf = 0; mf < 4; mf++) ldsm4(a[mf], rA[mf] + swA);
#pragma unroll
            for (int h = 0; h < 2; h++) {
                ldsm4(bg[h], rBg[h] + swB);
                ldsm4(bu[h], rBu[h] + swB);
            }
#pragma unroll
            for (int mf = 0; mf < 4; mf++)
#pragma unroll
                for (int h = 0; h < 2; h++) {
                    mma8(accG[mf][2 * h],     a[mf], bg[h][0], bg[h][1]);
                    mma8(accG[mf][2 * h + 1], a[mf], bg[h][2], bg[h][3]);
                    mma8(accU[mf][2 * h],     a[mf], bu[h][0], bu[h][1]);
                    mma8(accU[mf][2 * h + 1], a[mf], bu[h][2], bu[h][3]);
                }
            if (c == 1 && more) {
#pragma unroll
                for (int p = 0; p < 4; p++) {
                    pg[p] = gg4[(size_t)p * 16384 + (kt + 1) * 8];
                    pu[p] = uu4[(size_t)p * 16384 + (kt + 1) * 8];
                }
            }
        }
        if (more) {
#pragma unroll
            for (int p = 0; p < 4; p++) {
                *reinterpret_cast<uint4*>(smem + nxt + oG[p]) = tf4(pg[p]);
                *reinterpret_cast<uint4*>(smem + nxt + oU[p]) = tf4(pu[p]);
            }
        }
        cp_wait0();
        __syncthreads();
    }

    // ---- SwiGLU epilogue -> g_h (tf32-rounded) ----
#pragma unroll
    for (int mf = 0; mf < 4; mf++) {
#pragma unroll
        for (int half = 0; half < 2; half++) {
            const int grow = row0 + wm + mf * 16 + half * 8 + lr;
            if (grow >= cnt) continue;
            float* hrow = g_h + ((size_t)e * CAP + grow) * Ndim;
#pragma unroll
            for (int nf = 0; nf < 4; nf++) {
                const int col = n0 + wn + nf * 8 + 2 * lc;
                float2 o;
#pragma unroll
                for (int q = 0; q < 2; q++) {
                    float g = fminf(accG[mf][nf][half * 2 + q], 10.f);
                    float u = fminf(fmaxf(accU[mf][nf][half * 2 + q], -10.f), 10.f);
                    float h = (g / (1.f + expf(-g))) * u;
                    (&o.x)[q] = __uint_as_float(f2tf(h));
                }
                *reinterpret_cast<float2*>(hrow + col) = o;
            }
        }
    }
}

// ---------------------------------------------------------------------------
// Kernel gemm2: down, block 128 rows x 256 k-out, BK=32 (over N).
// 8 warps as 2x4; warp tile 64x64. A via cp.async from g_h.
// ---------------------------------------------------------------------------
constexpr int G2_A = 0, G2_B = 16384, G2_STAGE = 49152;
constexpr int G2_SMEM = 2 * G2_STAGE;   // 96 KB

__global__ __launch_bounds__(256)
void k_gemm2(const float* __restrict__ DW, float* __restrict__ out) {
    extern __shared__ char smem[];
    const int e    = blockIdx.z;
    const int cnt  = min(g_count[e], CAP);
    const int row0 = blockIdx.y * 128;
    if (row0 >= cnt) return;
    const int k0  = blockIdx.x * 256;
    const int tid = threadIdx.x;
    const uint32_t sb = smem_u32(smem);

    const int srow = tid >> 3, schk = tid & 7;
    const int swz  = ((schk ^ (srow & 7)) << 4);
    int oA[4], oB[8];
#pragma unroll
    for (int p = 0; p < 4; p++) oA[p] = G2_A + (srow + 32 * p) * 128 + swz;
#pragma unroll
    for (int p = 0; p < 8; p++) oB[p] = G2_B + (srow + 32 * p) * 128 + swz;
    const float* ha = g_h + ((size_t)e * CAP + row0 + srow) * Ndim + schk * 4;
    const float4* db4 = reinterpret_cast<const float4*>(
        DW + ((size_t)e * Kdim + k0 + srow) * Ndim) + schk;

    const int wid = tid >> 5, L = tid & 31;
    const int wm = (wid >> 2) * 64, wn = (wid & 3) * 64;
    const int lr = L >> 2, lc = L & 3;
    const int rowoffA = ((L >> 3) & 1) * 8 + (L & 7);
    const int hiA = L >> 4;
    const int rowoffB = ((L >> 4) & 1) * 8 + (L & 7);
    const int hiB = (L >> 3) & 1;
    const int lx = L & 7;
    uint32_t rA[4], rB[4];
#pragma unroll
    for (int mf = 0; mf < 4; mf++)
        rA[mf] = sb + G2_A + (wm + mf * 16 + rowoffA) * 128;
#pragma unroll
    for (int h = 0; h < 4; h++)
        rB[h] = sb + G2_B + (wn + h * 16 + rowoffB) * 128;

    float acc[4][8][4];
#pragma unroll
    for (int mf = 0; mf < 4; mf++)
#pragma unroll
        for (int nf = 0; nf < 8; nf++)
#pragma unroll
            for (int q = 0; q < 4; q++) acc[mf][nf][q] = 0.f;

    // prologue stage 0
#pragma unroll
    for (int p = 0; p < 4; p++) cp16(sb + oA[p], ha + (size_t)p * 32 * Ndim);
    cp_commit();
    float4 pb[8];
#pragma unroll
    for (int p = 0; p < 8; p++) pb[p] = db4[(size_t)p * 11264];
#pragma unroll
    for (int p = 0; p < 8; p++)
        *reinterpret_cast<uint4*>(smem + oB[p]) = tf4(pb[p]);
    cp_wait0();
    __syncthreads();

    const int KT = Ndim / 32;   // 44
    for (int kt = 0; kt < KT; ++kt) {
        const int cur = (kt & 1) * G2_STAGE;
        const int nxt = ((kt + 1) & 1) * G2_STAGE;
        const bool more = (kt + 1 < KT);
        if (more) {
#pragma unroll
            for (int p = 0; p < 4; p++)
                cp16(sb + nxt + oA[p], ha + (size_t)p * 32 * Ndim + (kt + 1) * 32);
            cp_commit();
        }
#pragma unroll
        for (int c = 0; c < 4; c++) {
            uint32_t a[4][4], b[4][4];
            const uint32_t swA = (uint32_t)(((2 * c + hiA) ^ lx) << 4) + cur;
            const uint32_t swB = (uint32_t)(((2 * c + hiB) ^ lx) << 4) + cur;
#pragma unroll
            for (int mf = 0; mf < 4; mf++) ldsm4(a[mf], rA[mf] + swA);
#pragma unroll
            for (int h = 0; h < 4; h++) ldsm4(b[h], rB[h] + swB);
#pragma unroll
            for (int mf = 0; mf < 4; mf++)
#pragma unroll
                for (int h = 0; h < 4; h++) {
                    mma8(acc[mf][2 * h],     a[mf], b[h][0], b[h][1]);
                    mma8(acc[mf][2 * h + 1], a[mf], b[h][2], b[h][3]);
                }
            if (c == 1 && more) {
#pragma unroll
                for (int p = 0; p < 8; p++)
                    pb[p] = db4[(size_t)p * 11264 + (kt + 1) * 8];
            }
        }
        if (more) {
#pragma unroll
            for (int p = 0; p < 8; p++)
                *reinterpret_cast<uint4*>(smem + nxt + oB[p]) = tf4(pb[p]);
        }
        cp_wait0();
        __syncthreads();
    }

    // ---- gated atomic scatter-combine ----
#pragma unroll
    for (int mf = 0; mf < 4; mf++) {
#pragma unroll
        for (int half = 0; half < 2; half++) {
            const int grow = row0 + wm + mf * 16 + half * 8 + lr;
            if (grow >= cnt) continue;
            const int   tok  = g_rowtok[e * CAP + grow];
            const float gate = g_rowgate[e * CAP + grow];
            float* orow = out + (size_t)tok * Kdim + k0;
#pragma unroll
            for (int nf = 0; nf < 8; nf++) {
                const int col = wn + nf * 8 + 2 * lc;
                atomicAdd(orow + col,     gate * acc[mf][nf][half * 2]);
                atomicAdd(orow + col + 1, gate * acc[mf][nf][half * 2 + 1]);
            }
        }
    }
}

// ---------------------------------------------------------------------------
// Launch
// ---------------------------------------------------------------------------
extern "C" void kernel_launch(void* const* d_in, const int* in_sizes, int n_in,
                              void* d_out, int out_size) {
    const float* X    = (const float*)d_in[0];
    const int*   fidx = (const int*)  d_in[1];
    const float* fg   = (const float*)d_in[2];
    const float* GW   = (const float*)d_in[3];
    const float* UW   = (const float*)d_in[4];
    const float* DW   = (const float*)d_in[5];
    float* out = (float*)d_out;

    cudaFuncSetAttribute(k_gemm1, cudaFuncAttributeMaxDynamicSharedMemorySize, G1_SMEM);
    cudaFuncSetAttribute(k_gemm2, cudaFuncAttributeMaxDynamicSharedMemorySize, G2_SMEM);

    k_zero<<<(Mtok * Kdim / 4 + 255) / 256, 256>>>(out);
    k_xround<<<(Mtok * Kdim / 4 + 255) / 256, 256>>>(X);
    k_route<<<(RROWS + 255) / 256, 256>>>(fidx, fg);

    dim3 g1(Ndim / 128, CAP / 128, NE);   // 11 x 8 x 8
    k_gemm1<<<g1, 256, G1_SMEM>>>(GW, UW);

    dim3 g2(Kdim / 256, CAP / 128, NE);   // 8 x 8 x 8
    k_gemm2<<<g2, 256, G2_SMEM>>>(DW, out);
}

// round 10
// speedup vs baseline: 3.5418x; 1.5767x over previous
#include <cuda_runtime.h>
#include <cstdint>
#include <math.h>

// ---------------------------------------------------------------------------
// Problem constants
// ---------------------------------------------------------------------------
constexpr int Mtok  = 2048;
constexpr int Kdim  = 2048;
constexpr int Ndim  = 1408;
constexpr int NE    = 8;
constexpr int CAP   = 1024;
constexpr int RROWS = 4096;

// Scratch
__device__ int   g_count[NE];
__device__ int   g_rowtok[NE * CAP];
__device__ float g_rowgate[NE * CAP];
__device__ float g_xr[(size_t)Mtok * Kdim];      // tf32-rounded X
__device__ float g_h[(size_t)NE * CAP * Ndim];   // tf32-rounded activations

// ---------------------------------------------------------------------------
// Helpers
// ---------------------------------------------------------------------------
__device__ __forceinline__ uint32_t smem_u32(const void* p) {
    uint32_t a;
    asm("{ .reg .u64 t; cvta.to.shared.u64 t, %1; cvt.u32.u64 %0, t; }"
        : "=r"(a) : "l"(p));
    return a;
}
__device__ __forceinline__ uint32_t f2tf(float x) {
    uint32_t r; asm("cvt.rna.tf32.f32 %0, %1;" : "=r"(r) : "f"(x)); return r;
}
__device__ __forceinline__ uint4 tf4(float4 v) {
    return make_uint4(f2tf(v.x), f2tf(v.y), f2tf(v.z), f2tf(v.w));
}
__device__ __forceinline__ void mma8(float c[4], const uint32_t a[4],
                                     uint32_t b0, uint32_t b1) {
    asm volatile(
        "mma.sync.aligned.m16n8k8.row.col.f32.tf32.tf32.f32 "
        "{%0,%1,%2,%3}, {%4,%5,%6,%7}, {%8,%9}, {%0,%1,%2,%3};"
        : "+f"(c[0]), "+f"(c[1]), "+f"(c[2]), "+f"(c[3])
        : "r"(a[0]), "r"(a[1]), "r"(a[2]), "r"(a[3]), "r"(b0), "r"(b1));
}
__device__ __forceinline__ void ldsm4(uint32_t* r, uint32_t addr) {
    asm volatile("ldmatrix.sync.aligned.m8n8.x4.shared.b16 {%0,%1,%2,%3}, [%4];"
                 : "=r"(r[0]), "=r"(r[1]), "=r"(r[2]), "=r"(r[3]) : "r"(addr));
}
__device__ __forceinline__ void cp16(uint32_t dst, const void* src) {
    asm volatile("cp.async.cg.shared.global [%0], [%1], 16;"
                 :: "r"(dst), "l"(src));
}
__device__ __forceinline__ void cp_commit() {
    asm volatile("cp.async.commit_group;" ::: "memory");
}
__device__ __forceinline__ void cp_wait0() {
    asm volatile("cp.async.wait_group 0;" ::: "memory");
}
// 256B-row swizzle: 16 chunks of 16B; keep bit3, XOR low3 with row&7
__device__ __forceinline__ int sw256(int chunk, int row) {
    return ((chunk & 8) | ((chunk & 7) ^ (row & 7))) << 4;
}

// ---------------------------------------------------------------------------
// Small kernels
// ---------------------------------------------------------------------------
__global__ void k_zero(float* __restrict__ out) {
    int idx = blockIdx.x * blockDim.x + threadIdx.x;
    if (idx < Mtok * Kdim / 4)
        reinterpret_cast<float4*>(out)[idx] = make_float4(0.f, 0.f, 0.f, 0.f);
    if (idx < NE) g_count[idx] = 0;
}
__global__ void k_xround(const float* __restrict__ X) {
    int idx = blockIdx.x * blockDim.x + threadIdx.x;
    if (idx < Mtok * Kdim / 4)
        reinterpret_cast<uint4*>(g_xr)[idx] =
            tf4(reinterpret_cast<const float4*>(X)[idx]);
}
__global__ void k_route(const int* __restrict__ flat_idx,
                        const float* __restrict__ flat_gate) {
    int r = blockIdx.x * blockDim.x + threadIdx.x;
    if (r >= RROWS) return;
    int e = flat_idx[r];
    if (e < 0 || e >= NE) return;
    int pos = atomicAdd(&g_count[e], 1);
    if (pos < CAP) {
        g_rowtok[e * CAP + pos]  = r >> 1;
        g_rowgate[e * CAP + pos] = flat_gate[r];
    }
}

// ---------------------------------------------------------------------------
// gemm1: gate+up. Block 128 rows x 128 n, BK=64 (8 k8-chunks/stage).
// Warp grid 2x4; warp tile 64 rows x 32 n per matrix (G and U).
// ---------------------------------------------------------------------------
constexpr int G1_A = 0, G1_BG = 32768, G1_BU = 65536, G1_STAGE = 98304;
constexpr int G1_SMEM = 2 * G1_STAGE;   // 192 KB

__global__ __launch_bounds__(256)
void k_gemm1(const float* __restrict__ GW, const float* __restrict__ UW) {
    extern __shared__ char smem[];
    const int e    = blockIdx.z;
    const int cnt  = min(g_count[e], CAP);
    const int row0 = blockIdx.y * 128;
    if (row0 >= cnt) return;
    const int n0  = blockIdx.x * 128;
    const int tid = threadIdx.x;
    const uint32_t sb = smem_u32(smem);

    // ---- staging ids: rows srow+32p, chunks schk & schk+8 ----
    const int srow = tid >> 3, schk = tid & 7;
    int oA[4][2], oW[4][2];           // smem offsets (A-layout rows / weight rows)
    const float* asrc[4];
    const float* gsrc[4];
    const float* usrc[4];
#pragma unroll
    for (int p = 0; p < 4; p++) {
        const int r = srow + 32 * p;
#pragma unroll
        for (int j = 0; j < 2; j++) {
            oA[p][j] = r * 256 + sw256(schk + 8 * j, r);
            oW[p][j] = oA[p][j];
        }
        int tok = g_rowtok[e * CAP + row0 + r];
        asrc[p] = g_xr + (size_t)tok * Kdim + schk * 4;
        gsrc[p] = GW + ((size_t)e * Ndim + n0 + r) * Kdim + schk * 4;
        usrc[p] = UW + ((size_t)e * Ndim + n0 + r) * Kdim + schk * 4;
    }

    // ---- compute ids ----
    const int wid = tid >> 5, L = tid & 31;
    const int wm = (wid >> 2) * 64, wn = (wid & 3) * 32;
    const int lr = L >> 2, lc = L & 3;
    const int rowoffA = ((L >> 3) & 1) * 8 + (L & 7);
    const int hiA = L >> 4;
    const int rowoffB = ((L >> 4) & 1) * 8 + (L & 7);
    const int hiB = (L >> 3) & 1;
    const int lx = L & 7;
    uint32_t rA[4], rBg[2], rBu[2];
#pragma unroll
    for (int mf = 0; mf < 4; mf++)
        rA[mf] = sb + G1_A + (wm + mf * 16 + rowoffA) * 256;
#pragma unroll
    for (int h = 0; h < 2; h++) {
        rBg[h] = sb + G1_BG + (wn + h * 16 + rowoffB) * 256;
        rBu[h] = sb + G1_BU + (wn + h * 16 + rowoffB) * 256;
    }

    float accG[4][4][4], accU[4][4][4];
#pragma unroll
    for (int mf = 0; mf < 4; mf++)
#pragma unroll
        for (int nf = 0; nf < 4; nf++)
#pragma unroll
            for (int q = 0; q < 4; q++) { accG[mf][nf][q] = 0.f; accU[mf][nf][q] = 0.f; }

    // ---- prologue: stage 0 ----
#pragma unroll
    for (int p = 0; p < 4; p++)
#pragma unroll
        for (int j = 0; j < 2; j++)
            cp16(sb + G1_A + oA[p][j], asrc[p] + 32 * j);
    cp_commit();
    {
        float4 w[4][2];
#pragma unroll
        for (int p = 0; p < 4; p++)
#pragma unroll
            for (int j = 0; j < 2; j++)
                w[p][j] = *reinterpret_cast<const float4*>(gsrc[p] + 32 * j);
#pragma unroll
        for (int p = 0; p < 4; p++)
#pragma unroll
            for (int j = 0; j < 2; j++)
                *reinterpret_cast<uint4*>(smem + G1_BG + oW[p][j]) = tf4(w[p][j]);
#pragma unroll
        for (int p = 0; p < 4; p++)
#pragma unroll
            for (int j = 0; j < 2; j++)
                w[p][j] = *reinterpret_cast<const float4*>(usrc[p] + 32 * j);
#pragma unroll
        for (int p = 0; p < 4; p++)
#pragma unroll
            for (int j = 0; j < 2; j++)
                *reinterpret_cast<uint4*>(smem + G1_BU + oW[p][j]) = tf4(w[p][j]);
    }
    cp_wait0();
    __syncthreads();

    const int KT = Kdim / 64;   // 32 stages
    float4 wst[4][2];
    for (int kt = 0; kt < KT; ++kt) {
        const int cur = (kt & 1) * G1_STAGE;
        const int nxt = ((kt + 1) & 1) * G1_STAGE;
        const bool more = (kt + 1 < KT);
        const int ko = (kt + 1) * 64;
        if (more) {
#pragma unroll
            for (int p = 0; p < 4; p++)
#pragma unroll
                for (int j = 0; j < 2; j++)
                    cp16(sb + nxt + G1_A + oA[p][j], asrc[p] + ko + 32 * j);
            cp_commit();
        }
#pragma unroll
        for (int c = 0; c < 8; c++) {
            uint32_t a[4][4], bg[2][4], bu[2][4];
            const uint32_t swA = (uint32_t)((((2 * c + hiA) & 8) |
                                            (((2 * c + hiA) & 7) ^ lx)) << 4) + cur;
            const uint32_t swB = (uint32_t)((((2 * c + hiB) & 8) |
                                            (((2 * c + hiB) & 7) ^ lx)) << 4) + cur;
#pragma unroll
            for (int mf = 0; mf < 4; mf++) ldsm4(a[mf], rA[mf] + swA);
#pragma unroll
            for (int h = 0; h < 2; h++) {
                ldsm4(bg[h], rBg[h] + swB);
                ldsm4(bu[h], rBu[h] + swB);
            }
#pragma unroll
            for (int mf = 0; mf < 4; mf++)
#pragma unroll
                for (int h = 0; h < 2; h++) {
                    mma8(accG[mf][2 * h],     a[mf], bg[h][0], bg[h][1]);
                    mma8(accG[mf][2 * h + 1], a[mf], bg[h][2], bg[h][3]);
                    mma8(accU[mf][2 * h],     a[mf], bu[h][0], bu[h][1]);
                    mma8(accU[mf][2 * h + 1], a[mf], bu[h][2], bu[h][3]);
                }
            // weight staging for stage kt+1, spread across chunks
            if (more) {
                if (c == 0) {
#pragma unroll
                    for (int p = 0; p < 4; p++)
#pragma unroll
                        for (int j = 0; j < 2; j++)
                            wst[p][j] = *reinterpret_cast<const float4*>(gsrc[p] + ko + 32 * j);
                } else if (c == 2) {
#pragma unroll
                    for (int p = 0; p < 4; p++)
#pragma unroll
                        for (int j = 0; j < 2; j++)
                            *reinterpret_cast<uint4*>(smem + nxt + G1_BG + oW[p][j]) = tf4(wst[p][j]);
#pragma unroll
                    for (int p = 0; p < 4; p++)
#pragma unroll
                        for (int j = 0; j < 2; j++)
                            wst[p][j] = *reinterpret_cast<const float4*>(usrc[p] + ko + 32 * j);
                } else if (c == 4) {
#pragma unroll
                    for (int p = 0; p < 4; p++)
#pragma unroll
                        for (int j = 0; j < 2; j++)
                            *reinterpret_cast<uint4*>(smem + nxt + G1_BU + oW[p][j]) = tf4(wst[p][j]);
                }
            }
        }
        cp_wait0();
        __syncthreads();
    }

    // ---- SwiGLU epilogue -> g_h (tf32-rounded) ----
#pragma unroll
    for (int mf = 0; mf < 4; mf++) {
#pragma unroll
        for (int half = 0; half < 2; half++) {
            const int grow = row0 + wm + mf * 16 + half * 8 + lr;
            if (grow >= cnt) continue;
            float* hrow = g_h + ((size_t)e * CAP + grow) * Ndim;
#pragma unroll
            for (int nf = 0; nf < 4; nf++) {
                const int col = n0 + wn + nf * 8 + 2 * lc;
                float2 o;
#pragma unroll
                for (int q = 0; q < 2; q++) {
                    float g = fminf(accG[mf][nf][half * 2 + q], 10.f);
                    float u = fminf(fmaxf(accU[mf][nf][half * 2 + q], -10.f), 10.f);
                    float h = (g / (1.f + expf(-g))) * u;
                    (&o.x)[q] = __uint_as_float(f2tf(h));
                }
                *reinterpret_cast<float2*>(hrow + col) = o;
            }
        }
    }
}

// ---------------------------------------------------------------------------
// gemm2: down. Block 128 rows x 256 k-out, BK=64 over N (8 k8-chunks/stage).
// Warp grid 2x4; warp tile 64x64.
// ---------------------------------------------------------------------------
constexpr int G2_A = 0, G2_B = 32768, G2_STAGE = 98304;
constexpr int G2_SMEM = 2 * G2_STAGE;   // 192 KB

__global__ __launch_bounds__(256)
void k_gemm2(const float* __restrict__ DW, float* __restrict__ out) {
    extern __shared__ char smem[];
    const int e    = blockIdx.z;
    const int cnt  = min(g_count[e], CAP);
    const int row0 = blockIdx.y * 128;
    if (row0 >= cnt) return;
    const int k0  = blockIdx.x * 256;
    const int tid = threadIdx.x;
    const uint32_t sb = smem_u32(smem);

    const int srow = tid >> 3, schk = tid & 7;
    int oA[4][2], oB[8][2];
    const float* ha[4];
    const float* bsrc[8];
#pragma unroll
    for (int p = 0; p < 4; p++) {
        const int r = srow + 32 * p;
#pragma unroll
        for (int j = 0; j < 2; j++) oA[p][j] = r * 256 + sw256(schk + 8 * j, r);
        ha[p] = g_h + ((size_t)e * CAP + row0 + r) * Ndim + schk * 4;
    }
#pragma unroll
    for (int p = 0; p < 8; p++) {
        const int r = srow + 32 * p;
#pragma unroll
        for (int j = 0; j < 2; j++) oB[p][j] = r * 256 + sw256(schk + 8 * j, r);
        bsrc[p] = DW + ((size_t)e * Kdim + k0 + r) * Ndim + schk * 4;
    }

    const int wid = tid >> 5, L = tid & 31;
    const int wm = (wid >> 2) * 64, wn = (wid & 3) * 64;
    const int lr = L >> 2, lc = L & 3;
    const int rowoffA = ((L >> 3) & 1) * 8 + (L & 7);
    const int hiA = L >> 4;
    const int rowoffB = ((L >> 4) & 1) * 8 + (L & 7);
    const int hiB = (L >> 3) & 1;
    const int lx = L & 7;
    uint32_t rA[4], rB[4];
#pragma unroll
    for (int mf = 0; mf < 4; mf++)
        rA[mf] = sb + G2_A + (wm + mf * 16 + rowoffA) * 256;
#pragma unroll
    for (int h = 0; h < 4; h++)
        rB[h] = sb + G2_B + (wn + h * 16 + rowoffB) * 256;

    float acc[4][8][4];
#pragma unroll
    for (int mf = 0; mf < 4; mf++)
#pragma unroll
        for (int nf = 0; nf < 8; nf++)
#pragma unroll
            for (int q = 0; q < 4; q++) acc[mf][nf][q] = 0.f;

    // prologue stage 0
#pragma unroll
    for (int p = 0; p < 4; p++)
#pragma unroll
        for (int j = 0; j < 2; j++)
            cp16(sb + G2_A + oA[p][j], ha[p] + 32 * j);
    cp_commit();
    {
        float4 w;
#pragma unroll
        for (int p = 0; p < 8; p++)
#pragma unroll
            for (int j = 0; j < 2; j++) {
                w = *reinterpret_cast<const float4*>(bsrc[p] + 32 * j);
                *reinterpret_cast<uint4*>(smem + G2_B + oB[p][j]) = tf4(w);
            }
    }
    cp_wait0();
    __syncthreads();

    const int KT = Ndim / 64;   // 22 stages
    float4 wst[4][2];
    for (int kt = 0; kt < KT; ++kt) {
        const int cur = (kt & 1) * G2_STAGE;
        const int nxt = ((kt + 1) & 1) * G2_STAGE;
        const bool more = (kt + 1 < KT);
        const int ko = (kt + 1) * 64;
        if (more) {
#pragma unroll
            for (int p = 0; p < 4; p++)
#pragma unroll
                for (int j = 0; j < 2; j++)
                    cp16(sb + nxt + G2_A + oA[p][j], ha[p] + ko + 32 * j);
            cp_commit();
        }
#pragma unroll
        for (int c = 0; c < 8; c++) {
            uint32_t a[4][4], b[4][4];
            const uint32_t swA = (uint32_t)((((2 * c + hiA) & 8) |
                                            (((2 * c + hiA) & 7) ^ lx)) << 4) + cur;
            const uint32_t swB = (uint32_t)((((2 * c + hiB) & 8) |
                                            (((2 * c + hiB) & 7) ^ lx)) << 4) + cur;
#pragma unroll
            for (int mf = 0; mf < 4; mf++) ldsm4(a[mf], rA[mf] + swA);
#pragma unroll
            for (int h = 0; h < 4; h++) ldsm4(b[h], rB[h] + swB);
#pragma unroll
            for (int mf = 0; mf < 4; mf++)
#pragma unroll
                for (int h = 0; h < 4; h++) {
                    mma8(acc[mf][2 * h],     a[mf], b[h][0], b[h][1]);
                    mma8(acc[mf][2 * h + 1], a[mf], b[h][2], b[h][3]);
                }
            if (more) {
                if (c == 0) {
#pragma unroll
                    for (int p = 0; p < 4; p++)
#pragma unroll
                        for (int j = 0; j < 2; j++)
                            wst[p][j] = *reinterpret_cast<const float4*>(bsrc[p] + ko + 32 * j);
                } else if (c == 2) {
#pragma unroll
                    for (int p = 0; p < 4; p++)
#pragma unroll
                        for (int j = 0; j < 2; j++)
                            *reinterpret_cast<uint4*>(smem + nxt + G2_B + oB[p][j]) = tf4(wst[p][j]);
#pragma unroll
                    for (int p = 0; p < 4; p++)
#pragma unroll
                        for (int j = 0; j < 2; j++)
                            wst[p][j] = *reinterpret_cast<const float4*>(bsrc[p + 4] + ko + 32 * j);
                } else if (c == 4) {
#pragma unroll
                    for (int p = 0; p < 4; p++)
#pragma unroll
                        for (int j = 0; j < 2; j++)
                            *reinterpret_cast<uint4*>(smem + nxt + G2_B + oB[p + 4][j]) = tf4(wst[p][j]);
                }
            }
        }
        cp_wait0();
        __syncthreads();
    }

    // ---- gated atomic scatter-combine ----
#pragma unroll
    for (int mf = 0; mf < 4; mf++) {
#pragma unroll
        for (int half = 0; half < 2; half++) {
            const int grow = row0 + wm + mf * 16 + half * 8 + lr;
            if (grow >= cnt) continue;
            const int   tok  = g_rowtok[e * CAP + grow];
            const float gate = g_rowgate[e * CAP + grow];
            float* orow = out + (size_t)tok * Kdim + k0;
#pragma unroll
            for (int nf = 0; nf < 8; nf++) {
                const int col = wn + nf * 8 + 2 * lc;
                atomicAdd(orow + col,     gate * acc[mf][nf][half * 2]);
                atomicAdd(orow + col + 1, gate * acc[mf][nf][half * 2 + 1]);
            }
        }
    }
}

// ---------------------------------------------------------------------------
// Launch
// ---------------------------------------------------------------------------
extern "C" void kernel_launch(void* const* d_in, const int* in_sizes, int n_in,
                              void* d_out, int out_size) {
    const float* X    = (const float*)d_in[0];
    const int*   fidx = (const int*)  d_in[1];
    const float* fg   = (const float*)d_in[2];
    const float* GW   = (const float*)d_in[3];
    const float* UW   = (const float*)d_in[4];
    const float* DW   = (const float*)d_in[5];
    float* out = (float*)d_out;

    cudaFuncSetAttribute(k_gemm1, cudaFuncAttributeMaxDynamicSharedMemorySize, G1_SMEM);
    cudaFuncSetAttribute(k_gemm2, cudaFuncAttributeMaxDynamicSharedMemorySize, G2_SMEM);

    k_zero<<<(Mtok * Kdim / 4 + 255) / 256, 256>>>(out);
    k_xround<<<(Mtok * Kdim / 4 + 255) / 256, 256>>>(X);
    k_route<<<(RROWS + 255) / 256, 256>>>(fidx, fg);

    dim3 g1(Ndim / 128, CAP / 128, NE);   // 11 x 8 x 8
    k_gemm1<<<g1, 256, G1_SMEM>>>(GW, UW);

    dim3 g2(Kdim / 256, CAP / 128, NE);   // 8 x 8 x 8
    k_gemm2<<<g2, 256, G2_SMEM>>>(DW, out);
}

// round 13
// speedup vs baseline: 3.6055x; 1.0180x over previous
#include <cuda_runtime.h>
#include <cstdint>
#include <math.h>

// ---------------------------------------------------------------------------
// Problem constants
// ---------------------------------------------------------------------------
constexpr int Mtok  = 2048;
constexpr int Kdim  = 2048;
constexpr int Ndim  = 1408;
constexpr int NE    = 8;
constexpr int CAP   = 1024;
constexpr int RROWS = 4096;

// Scratch
__device__ int   g_count[NE];
__device__ int   g_rowtok[NE * CAP];
__device__ float g_rowgate[NE * CAP];
__device__ float g_xr[(size_t)Mtok * Kdim];      // tf32-rounded X
__device__ float g_h[(size_t)NE * CAP * Ndim];   // tf32-rounded activations

// ---------------------------------------------------------------------------
// Helpers
// ---------------------------------------------------------------------------
__device__ __forceinline__ uint32_t smem_u32(const void* p) {
    uint32_t a;
    asm("{ .reg .u64 t; cvta.to.shared.u64 t, %1; cvt.u32.u64 %0, t; }"
        : "=r"(a) : "l"(p));
    return a;
}
__device__ __forceinline__ uint32_t f2tf(float x) {
    uint32_t r; asm("cvt.rna.tf32.f32 %0, %1;" : "=r"(r) : "f"(x)); return r;
}
__device__ __forceinline__ uint4 tf4(float4 v) {
    return make_uint4(f2tf(v.x), f2tf(v.y), f2tf(v.z), f2tf(v.w));
}
__device__ __forceinline__ void mma8(float c[4], const uint32_t a[4],
                                     uint32_t b0, uint32_t b1) {
    asm volatile(
        "mma.sync.aligned.m16n8k8.row.col.f32.tf32.tf32.f32 "
        "{%0,%1,%2,%3}, {%4,%5,%6,%7}, {%8,%9}, {%0,%1,%2,%3};"
        : "+f"(c[0]), "+f"(c[1]), "+f"(c[2]), "+f"(c[3])
        : "r"(a[0]), "r"(a[1]), "r"(a[2]), "r"(a[3]), "r"(b0), "r"(b1));
}
__device__ __forceinline__ void ldsm4(uint32_t* r, uint32_t addr) {
    asm volatile("ldmatrix.sync.aligned.m8n8.x4.shared.b16 {%0,%1,%2,%3}, [%4];"
                 : "=r"(r[0]), "=r"(r[1]), "=r"(r[2]), "=r"(r[3]) : "r"(addr));
}
__device__ __forceinline__ void cp16(uint32_t dst, const void* src) {
    asm volatile("cp.async.cg.shared.global [%0], [%1], 16;"
                 :: "r"(dst), "l"(src));
}
__device__ __forceinline__ void cp_commit() {
    asm volatile("cp.async.commit_group;" ::: "memory");
}
__device__ __forceinline__ void cp_wait0() {
    asm volatile("cp.async.wait_group 0;" ::: "memory");
}
// 256B-row swizzle: 16 chunks of 16B; keep bit3, XOR low3 with row&7
__device__ __forceinline__ int sw256(int chunk, int row) {
    return ((chunk & 8) | ((chunk & 7) ^ (row & 7))) << 4;
}

// ---------------------------------------------------------------------------
// Prep kernels
// ---------------------------------------------------------------------------
__global__ void k_prep(float* __restrict__ out, const float* __restrict__ X) {
    int idx = blockIdx.x * blockDim.x + threadIdx.x;
    if (idx < Mtok * Kdim / 4) {
        reinterpret_cast<float4*>(out)[idx] = make_float4(0.f, 0.f, 0.f, 0.f);
        reinterpret_cast<uint4*>(g_xr)[idx] =
            tf4(reinterpret_cast<const float4*>(X)[idx]);
    }
    if (idx < NE) g_count[idx] = 0;
}
__global__ void k_route(const int* __restrict__ flat_idx,
                        const float* __restrict__ flat_gate) {
    int r = blockIdx.x * blockDim.x + threadIdx.x;
    if (r >= RROWS) return;
    int e = flat_idx[r];
    if (e < 0 || e >= NE) return;
    int pos = atomicAdd(&g_count[e], 1);
    if (pos < CAP) {
        g_rowtok[e * CAP + pos]  = r >> 1;
        g_rowgate[e * CAP + pos] = flat_gate[r];
    }
}

// ---------------------------------------------------------------------------
// gemm1: gate+up. Block 128 rows x 128 n, BK=64 (8 k8-chunks/stage).
// Warp grid 2x4; warp tile 64 rows x 32 n per matrix (G and U).
// Stage barrier hidden inside last chunk (between ldsm(7) and mma(7)).
// ---------------------------------------------------------------------------
constexpr int G1_A = 0, G1_BG = 32768, G1_BU = 65536, G1_STAGE = 98304;
constexpr int G1_SMEM = 2 * G1_STAGE;   // 192 KB

__global__ __launch_bounds__(256)
void k_gemm1(const float* __restrict__ GW, const float* __restrict__ UW) {
    extern __shared__ char smem[];
    const int e    = blockIdx.z;
    const int cnt  = min(g_count[e], CAP);
    const int row0 = blockIdx.y * 128;
    if (row0 >= cnt) return;
    const int n0  = blockIdx.x * 128;
    const int tid = threadIdx.x;
    const uint32_t sb = smem_u32(smem);

    // ---- staging ids: rows srow+32p, chunks schk & schk+8 ----
    const int srow = tid >> 3, schk = tid & 7;
    int oA[4][2], oW[4][2];
    const float* asrc[4];
    const float* gsrc[4];
    const float* usrc[4];
#pragma unroll
    for (int p = 0; p < 4; p++) {
        const int r = srow + 32 * p;
#pragma unroll
        for (int j = 0; j < 2; j++) {
            oA[p][j] = r * 256 + sw256(schk + 8 * j, r);
            oW[p][j] = oA[p][j];
        }
        int tok = g_rowtok[e * CAP + row0 + r];
        asrc[p] = g_xr + (size_t)tok * Kdim + schk * 4;
        gsrc[p] = GW + ((size_t)e * Ndim + n0 + r) * Kdim + schk * 4;
        usrc[p] = UW + ((size_t)e * Ndim + n0 + r) * Kdim + schk * 4;
    }

    // ---- compute ids ----
    const int wid = tid >> 5, L = tid & 31;
    const int wm = (wid >> 2) * 64, wn = (wid & 3) * 32;
    const int lr = L >> 2, lc = L & 3;
    const int rowoffA = ((L >> 3) & 1) * 8 + (L & 7);
    const int hiA = L >> 4;
    const int rowoffB = ((L >> 4) & 1) * 8 + (L & 7);
    const int hiB = (L >> 3) & 1;
    const int lx = L & 7;
    uint32_t rA[4], rBg[2], rBu[2];
#pragma unroll
    for (int mf = 0; mf < 4; mf++)
        rA[mf] = sb + G1_A + (wm + mf * 16 + rowoffA) * 256;
#pragma unroll
    for (int h = 0; h < 2; h++) {
        rBg[h] = sb + G1_BG + (wn + h * 16 + rowoffB) * 256;
        rBu[h] = sb + G1_BU + (wn + h * 16 + rowoffB) * 256;
    }

    float accG[4][4][4], accU[4][4][4];
#pragma unroll
    for (int mf = 0; mf < 4; mf++)
#pragma unroll
        for (int nf = 0; nf < 4; nf++)
#pragma unroll
            for (int q = 0; q < 4; q++) { accG[mf][nf][q] = 0.f; accU[mf][nf][q] = 0.f; }

    // ---- prologue: stage 0 ----
#pragma unroll
    for (int p = 0; p < 4; p++)
#pragma unroll
        for (int j = 0; j < 2; j++)
            cp16(sb + G1_A + oA[p][j], asrc[p] + 32 * j);
    cp_commit();
    {
        float4 w[4][2];
#pragma unroll
        for (int p = 0; p < 4; p++)
#pragma unroll
            for (int j = 0; j < 2; j++)
                w[p][j] = *reinterpret_cast<const float4*>(gsrc[p] + 32 * j);
#pragma unroll
        for (int p = 0; p < 4; p++)
#pragma unroll
            for (int j = 0; j < 2; j++)
                *reinterpret_cast<uint4*>(smem + G1_BG + oW[p][j]) = tf4(w[p][j]);
#pragma unroll
        for (int p = 0; p < 4; p++)
#pragma unroll
            for (int j = 0; j < 2; j++)
                w[p][j] = *reinterpret_cast<const float4*>(usrc[p] + 32 * j);
#pragma unroll
        for (int p = 0; p < 4; p++)
#pragma unroll
            for (int j = 0; j < 2; j++)
                *reinterpret_cast<uint4*>(smem + G1_BU + oW[p][j]) = tf4(w[p][j]);
    }
    cp_wait0();
    __syncthreads();

    const int KT = Kdim / 64;   // 32 stages
    float4 wst[4][2];
    for (int kt = 0; kt < KT; ++kt) {
        const int cur = (kt & 1) * G1_STAGE;
        const int nxt = ((kt + 1) & 1) * G1_STAGE;
        const bool more = (kt + 1 < KT);
        const int ko = (kt + 1) * 64;
        if (more) {
#pragma unroll
            for (int p = 0; p < 4; p++)
#pragma unroll
                for (int j = 0; j < 2; j++)
                    cp16(sb + nxt + G1_A + oA[p][j], asrc[p] + ko + 32 * j);
            cp_commit();
        }
#pragma unroll
        for (int c = 0; c < 8; c++) {
            uint32_t a[4][4], bg[2][4], bu[2][4];
            const uint32_t swA = (uint32_t)((((2 * c + hiA) & 8) |
                                            (((2 * c + hiA) & 7) ^ lx)) << 4) + cur;
            const uint32_t swB = (uint32_t)((((2 * c + hiB) & 8) |
                                            (((2 * c + hiB) & 7) ^ lx)) << 4) + cur;
#pragma unroll
            for (int mf = 0; mf < 4; mf++) ldsm4(a[mf], rA[mf] + swA);
#pragma unroll
            for (int h = 0; h < 2; h++) {
                ldsm4(bg[h], rBg[h] + swB);
                ldsm4(bu[h], rBu[h] + swB);
            }
            // Stage boundary: all reads of `cur` are done (this chunk's ldsm
            // above was the last). Barrier here is covered by chunk-6 mma in
            // the tensor queue; mma(7) below runs from registers post-barrier.
            if (c == 7) { cp_wait0(); __syncthreads(); }
#pragma unroll
            for (int mf = 0; mf < 4; mf++)
#pragma unroll
                for (int h = 0; h < 2; h++) {
                    mma8(accG[mf][2 * h],     a[mf], bg[h][0], bg[h][1]);
                    mma8(accG[mf][2 * h + 1], a[mf], bg[h][2], bg[h][3]);
                    mma8(accU[mf][2 * h],     a[mf], bu[h][0], bu[h][1]);
                    mma8(accU[mf][2 * h + 1], a[mf], bu[h][2], bu[h][3]);
                }
            // weight staging for stage kt+1, spread across chunks (all pre-barrier)
            if (more) {
                if (c == 0) {
#pragma unroll
                    for (int p = 0; p < 4; p++)
#pragma unroll
                        for (int j = 0; j < 2; j++)
                            wst[p][j] = *reinterpret_cast<const float4*>(gsrc[p] + ko + 32 * j);
                } else if (c == 2) {
#pragma unroll
                    for (int p = 0; p < 4; p++)
#pragma unroll
                        for (int j = 0; j < 2; j++)
                            *reinterpret_cast<uint4*>(smem + nxt + G1_BG + oW[p][j]) = tf4(wst[p][j]);
#pragma unroll
                    for (int p = 0; p < 4; p++)
#pragma unroll
                        for (int j = 0; j < 2; j++)
                            wst[p][j] = *reinterpret_cast<const float4*>(usrc[p] + ko + 32 * j);
                } else if (c == 4) {
#pragma unroll
                    for (int p = 0; p < 4; p++)
#pragma unroll
                        for (int j = 0; j < 2; j++)
                            *reinterpret_cast<uint4*>(smem + nxt + G1_BU + oW[p][j]) = tf4(wst[p][j]);
                }
            }
        }
    }

    // ---- SwiGLU epilogue -> g_h (tf32-rounded) ----
#pragma unroll
    for (int mf = 0; mf < 4; mf++) {
#pragma unroll
        for (int half = 0; half < 2; half++) {
            const int grow = row0 + wm + mf * 16 + half * 8 + lr;
            if (grow >= cnt) continue;
            float* hrow = g_h + ((size_t)e * CAP + grow) * Ndim;
#pragma unroll
            for (int nf = 0; nf < 4; nf++) {
                const int col = n0 + wn + nf * 8 + 2 * lc;
                float2 o;
#pragma unroll
                for (int q = 0; q < 2; q++) {
                    float g = fminf(accG[mf][nf][half * 2 + q], 10.f);
                    float u = fminf(fmaxf(accU[mf][nf][half * 2 + q], -10.f), 10.f);
                    float h = (g / (1.f + expf(-g))) * u;
                    (&o.x)[q] = __uint_as_float(f2tf(h));
                }
                *reinterpret_cast<float2*>(hrow + col) = o;
            }
        }
    }
}

// ---------------------------------------------------------------------------
// gemm2: down. Block 128 rows x 256 k-out, BK=64 over N (8 k8-chunks/stage).
// Warp grid 2x4; warp tile 64x64. Same hidden-barrier structure.
// ---------------------------------------------------------------------------
constexpr int G2_A = 0, G2_B = 32768, G2_STAGE = 98304;
constexpr int G2_SMEM = 2 * G2_STAGE;   // 192 KB

__global__ __launch_bounds__(256)
void k_gemm2(const float* __restrict__ DW, float* __restrict__ out) {
    extern __shared__ char smem[];
    const int e    = blockIdx.z;
    const int cnt  = min(g_count[e], CAP);
    const int row0 = blockIdx.y * 128;
    if (row0 >= cnt) return;
    const int k0  = blockIdx.x * 256;
    const int tid = threadIdx.x;
    const uint32_t sb = smem_u32(smem);

    const int srow = tid >> 3, schk = tid & 7;
    int oA[4][2], oB[8][2];
    const float* ha[4];
    const float* bsrc[8];
#pragma unroll
    for (int p = 0; p < 4; p++) {
        const int r = srow + 32 * p;
#pragma unroll
        for (int j = 0; j < 2; j++) oA[p][j] = r * 256 + sw256(schk + 8 * j, r);
        ha[p] = g_h + ((size_t)e * CAP + row0 + r) * Ndim + schk * 4;
    }
#pragma unroll
    for (int p = 0; p < 8; p++) {
        const int r = srow + 32 * p;
#pragma unroll
        for (int j = 0; j < 2; j++) oB[p][j] = r * 256 + sw256(schk + 8 * j, r);
        bsrc[p] = DW + ((size_t)e * Kdim + k0 + r) * Ndim + schk * 4;
    }

    const int wid = tid >> 5, L = tid & 31;
    const int wm = (wid >> 2) * 64, wn = (wid & 3) * 64;
    const int lr = L >> 2, lc = L & 3;
    const int rowoffA = ((L >> 3) & 1) * 8 + (L & 7);
    const int hiA = L >> 4;
    const int rowoffB = ((L >> 4) & 1) * 8 + (L & 7);
    const int hiB = (L >> 3) & 1;
    const int lx = L & 7;
    uint32_t rA[4], rB[4];
#pragma unroll
    for (int mf = 0; mf < 4; mf++)
        rA[mf] = sb + G2_A + (wm + mf * 16 + rowoffA) * 256;
#pragma unroll
    for (int h = 0; h < 4; h++)
        rB[h] = sb + G2_B + (wn + h * 16 + rowoffB) * 256;

    float acc[4][8][4];
#pragma unroll
    for (int mf = 0; mf < 4; mf++)
#pragma unroll
        for (int nf = 0; nf < 8; nf++)
#pragma unroll
            for (int q = 0; q < 4; q++) acc[mf][nf][q] = 0.f;

    // prologue stage 0
#pragma unroll
    for (int p = 0; p < 4; p++)
#pragma unroll
        for (int j = 0; j < 2; j++)
            cp16(sb + G2_A + oA[p][j], ha[p] + 32 * j);
    cp_commit();
    {
        float4 w;
#pragma unroll
        for (int p = 0; p < 8; p++)
#pragma unroll
            for (int j = 0; j < 2; j++) {
                w = *reinterpret_cast<const float4*>(bsrc[p] + 32 * j);
                *reinterpret_cast<uint4*>(smem + G2_B + oB[p][j]) = tf4(w);
            }
    }
    cp_wait0();
    __syncthreads();

    const int KT = Ndim / 64;   // 22 stages
    float4 wst[4][2];
    for (int kt = 0; kt < KT; ++kt) {
        const int cur = (kt & 1) * G2_STAGE;
        const int nxt = ((kt + 1) & 1) * G2_STAGE;
        const bool more = (kt + 1 < KT);
        const int ko = (kt + 1) * 64;
        if (more) {
#pragma unroll
            for (int p = 0; p < 4; p++)
#pragma unroll
                for (int j = 0; j < 2; j++)
                    cp16(sb + nxt + G2_A + oA[p][j], ha[p] + ko + 32 * j);
            cp_commit();
        }
#pragma unroll
        for (int c = 0; c < 8; c++) {
            uint32_t a[4][4], b[4][4];
            const uint32_t swA = (uint32_t)((((2 * c + hiA) & 8) |
                                            (((2 * c + hiA) & 7) ^ lx)) << 4) + cur;
            const uint32_t swB = (uint32_t)((((2 * c + hiB) & 8) |
                                            (((2 * c + hiB) & 7) ^ lx)) << 4) + cur;
#pragma unroll
            for (int mf = 0; mf < 4; mf++) ldsm4(a[mf], rA[mf] + swA);
#pragma unroll
            for (int h = 0; h < 4; h++) ldsm4(b[h], rB[h] + swB);
            if (c == 7) { cp_wait0(); __syncthreads(); }
#pragma unroll
            for (int mf = 0; mf < 4; mf++)
#pragma unroll
                for (int h = 0; h < 4; h++) {
                    mma8(acc[mf][2 * h],     a[mf], b[h][0], b[h][1]);
                    mma8(acc[mf][2 * h + 1], a[mf], b[h][2], b[h][3]);
                }
            if (more) {
                if (c == 0) {
#pragma unroll
                    for (int p = 0; p < 4; p++)
#pragma unroll
                        for (int j = 0; j < 2; j++)
                            wst[p][j] = *reinterpret_cast<const float4*>(bsrc[p] + ko + 32 * j);
                } else if (c == 2) {
#pragma unroll
                    for (int p = 0; p < 4; p++)
#pragma unroll
                        for (int j = 0; j < 2; j++)
                            *reinterpret_cast<uint4*>(smem + nxt + G2_B + oB[p][j]) = tf4(wst[p][j]);
#pragma unroll
                    for (int p = 0; p < 4; p++)
#pragma unroll
                        for (int j = 0; j < 2; j++)
                            wst[p][j] = *reinterpret_cast<const float4*>(bsrc[p + 4] + ko + 32 * j);
                } else if (c == 4) {
#pragma unroll
                    for (int p = 0; p < 4; p++)
#pragma unroll
                        for (int j = 0; j < 2; j++)
                            *reinterpret_cast<uint4*>(smem + nxt + G2_B + oB[p + 4][j]) = tf4(wst[p][j]);
                }
            }
        }
    }

    // ---- gated atomic scatter-combine ----
#pragma unroll
    for (int mf = 0; mf < 4; mf++) {
#pragma unroll
        for (int half = 0; half < 2; half++) {
            const int grow = row0 + wm + mf * 16 + half * 8 + lr;
            if (grow >= cnt) continue;
            const int   tok  = g_rowtok[e * CAP + grow];
            const float gate = g_rowgate[e * CAP + grow];
            float* orow = out + (size_t)tok * Kdim + k0;
#pragma unroll
            for (int nf = 0; nf < 8; nf++) {
                const int col = wn + nf * 8 + 2 * lc;
                atomicAdd(orow + col,     gate * acc[mf][nf][half * 2]);
                atomicAdd(orow + col + 1, gate * acc[mf][nf][half * 2 + 1]);
            }
        }
    }
}

// ---------------------------------------------------------------------------
// Launch
// ---------------------------------------------------------------------------
extern "C" void kernel_launch(void* const* d_in, const int* in_sizes, int n_in,
                              void* d_out, int out_size) {
    const float* X    = (const float*)d_in[0];
    const int*   fidx = (const int*)  d_in[1];
    const float* fg   = (const float*)d_in[2];
    const float* GW   = (const float*)d_in[3];
    const float* UW   = (const float*)d_in[4];
    const float* DW   = (const float*)d_in[5];
    float* out = (float*)d_out;

    cudaFuncSetAttribute(k_gemm1, cudaFuncAttributeMaxDynamicSharedMemorySize, G1_SMEM);
    cudaFuncSetAttribute(k_gemm2, cudaFuncAttributeMaxDynamicSharedMemorySize, G2_SMEM);

    k_prep<<<(Mtok * Kdim / 4 + 255) / 256, 256>>>(out, X);
    k_route<<<(RROWS + 255) / 256, 256>>>(fidx, fg);

    dim3 g1(Ndim / 128, CAP / 128, NE);   // 11 x 8 x 8
    k_gemm1<<<g1, 256, G1_SMEM>>>(GW, UW);

    dim3 g2(Kdim / 256, CAP / 128, NE);   // 8 x 8 x 8
    k_gemm2<<<g2, 256, G2_SMEM>>>(DW, out);
}